// round 1
// baseline (speedup 1.0000x reference)
#include <cuda_runtime.h>
#include <cuda_bf16.h>
#include <math.h>

// Problem constants
#define BB 4
#define NN 2048
#define CC 384
#define HH 8
#define HD 48
#define TT (BB * NN)          // 8192 tokens
#define SCALE 0.14433756729740645f  // 1/sqrt(48)

// Scratch (static device globals — no runtime allocation)
__device__ float g_Q[TT * CC];
__device__ float g_K[TT * CC];
__device__ float g_V[TT * CC];
__device__ float g_X[TT * CC];

// ---------------------------------------------------------------------------
// GEMM: out[m][n] = sum_k A[m][k] * W[n][k] + bias[n]
// A: [M, 384], W: [384, 384] (row-major; we dot rows of A with rows of W)
// Tiles: BM=64, BN=64, BK=16; 256 threads; 4x4 micro-tile per thread.
// Shared tiles stored K-major-transposed so micro-tile fragments are float4.
// ---------------------------------------------------------------------------
__global__ void gemm_nt_bias(const float* __restrict__ A,
                             const float* __restrict__ W,
                             const float* __restrict__ bias,
                             float* __restrict__ out)
{
    const int K = CC;
    __shared__ float As[16][68];  // [kk][row], stride 68 (16B-aligned rows, reduced store conflicts)
    __shared__ float Ws[16][68];  // [kk][col]

    int tid = threadIdx.x;          // 0..255
    int tx = tid & 15;              // column group
    int ty = tid >> 4;              // row group
    int row0 = blockIdx.y * 64;
    int col0 = blockIdx.x * 64;

    int lr = tid >> 2;              // 0..63 (row/col to load)
    int lk = (tid & 3) << 2;        // 0,4,8,12 (k offset)

    float acc[4][4];
#pragma unroll
    for (int i = 0; i < 4; i++)
#pragma unroll
        for (int j = 0; j < 4; j++) acc[i][j] = 0.f;

    for (int k0 = 0; k0 < K; k0 += 16) {
        float4 a = *(const float4*)(A + (size_t)(row0 + lr) * K + k0 + lk);
        float4 w = *(const float4*)(W + (size_t)(col0 + lr) * K + k0 + lk);
        __syncthreads();
        As[lk + 0][lr] = a.x; As[lk + 1][lr] = a.y;
        As[lk + 2][lr] = a.z; As[lk + 3][lr] = a.w;
        Ws[lk + 0][lr] = w.x; Ws[lk + 1][lr] = w.y;
        Ws[lk + 2][lr] = w.z; Ws[lk + 3][lr] = w.w;
        __syncthreads();

#pragma unroll
        for (int kk = 0; kk < 16; kk++) {
            float4 av = *(const float4*)&As[kk][ty * 4];
            float4 wv = *(const float4*)&Ws[kk][tx * 4];
            float ar[4] = {av.x, av.y, av.z, av.w};
            float wr[4] = {wv.x, wv.y, wv.z, wv.w};
#pragma unroll
            for (int i = 0; i < 4; i++)
#pragma unroll
                for (int j = 0; j < 4; j++)
                    acc[i][j] += ar[i] * wr[j];
        }
    }

    float4 bv = *(const float4*)(bias + col0 + tx * 4);
    float bb[4] = {bv.x, bv.y, bv.z, bv.w};
#pragma unroll
    for (int i = 0; i < 4; i++) {
        float4 r;
        r.x = acc[i][0] + bb[0];
        r.y = acc[i][1] + bb[1];
        r.z = acc[i][2] + bb[2];
        r.w = acc[i][3] + bb[3];
        *(float4*)(out + (size_t)(row0 + ty * 4 + i) * K + col0 + tx * 4) = r;
    }
}

// ---------------------------------------------------------------------------
// RoPE3D (in place). One thread handles one (token, head, axis) chunk of 16.
// out[j]   = x[j]*cos - x[j+8]*sin
// out[j+8] = x[j+8]*cos + x[j]*sin,  angle = pos * 100^(-j/8)
// ---------------------------------------------------------------------------
__global__ void rope3d_kernel(float* __restrict__ X, const int* __restrict__ pos)
{
    int idx = blockIdx.x * blockDim.x + threadIdx.x;  // TT*HH*3 = 196608
    if (idx >= TT * HH * 3) return;
    int a = idx % 3;
    int h = (idx / 3) % HH;
    int t = idx / (3 * HH);

    float p = (float)pos[t * 3 + a];
    float* x = X + (size_t)t * CC + h * HD + a * 16;

    float v[16];
#pragma unroll
    for (int c = 0; c < 4; c++) {
        float4 f = ((const float4*)x)[c];
        v[c * 4 + 0] = f.x; v[c * 4 + 1] = f.y; v[c * 4 + 2] = f.z; v[c * 4 + 3] = f.w;
    }

    const float LOG2_100 = 6.643856189774724f;
#pragma unroll
    for (int j = 0; j < 8; j++) {
        float inv = exp2f(-(float)j * 0.125f * LOG2_100);  // 100^(-j/8)
        float ang = p * inv;
        float sn, cs;
        sincosf(ang, &sn, &cs);
        float x1 = v[j], x2 = v[j + 8];
        v[j]     = x1 * cs - x2 * sn;
        v[j + 8] = x2 * cs + x1 * sn;
    }

#pragma unroll
    for (int c = 0; c < 4; c++) {
        float4 f;
        f.x = v[c * 4 + 0]; f.y = v[c * 4 + 1]; f.z = v[c * 4 + 2]; f.w = v[c * 4 + 3];
        ((float4*)x)[c] = f;
    }
}

// ---------------------------------------------------------------------------
// Attention: grid (N/128, H, B), 128 threads; thread = one query row.
// Online softmax with lazy max-rescale (rescale only when a new max appears —
// expected ~ln(N) times per thread, so the 48-FMA rescale is nearly free).
// K/V staged in shared as 64-key tiles of float4 (12 per row).
// ---------------------------------------------------------------------------
__global__ void attn_kernel(const float* __restrict__ Q,
                            const float* __restrict__ K,
                            const float* __restrict__ V,
                            float* __restrict__ X)
{
    __shared__ float4 Ks[64 * 12];
    __shared__ float4 Vs[64 * 12];

    int tid = threadIdx.x;                 // 0..127
    int b = blockIdx.z;
    int h = blockIdx.y;
    int qi = blockIdx.x * 128 + tid;       // query index within segment
    int t = b * NN + qi;

    // Load q row (48 floats)
    const float* qptr = Q + (size_t)t * CC + h * HD;
    float q[HD];
#pragma unroll
    for (int c = 0; c < 12; c++) {
        float4 f = ((const float4*)qptr)[c];
        q[c * 4 + 0] = f.x; q[c * 4 + 1] = f.y; q[c * 4 + 2] = f.z; q[c * 4 + 3] = f.w;
    }

    float m = -1e30f, l = 0.f;
    float o[HD];
#pragma unroll
    for (int d = 0; d < HD; d++) o[d] = 0.f;

    const size_t seg_base = (size_t)b * NN;

    for (int kt = 0; kt < NN; kt += 64) {
        __syncthreads();
        // Stage K and V tiles: 64 rows x 12 float4 each
        for (int e = tid; e < 768; e += 128) {
            int r = e / 12, c = e % 12;
            size_t off = (seg_base + kt + r) * CC + h * HD;
            Ks[e] = ((const float4*)(K + off))[c];
            Vs[e] = ((const float4*)(V + off))[c];
        }
        __syncthreads();

        for (int j = 0; j < 64; j++) {
            // s = q . k_j  (broadcast shared reads)
            float acc = 0.f;
#pragma unroll
            for (int c = 0; c < 12; c++) {
                float4 k4 = Ks[j * 12 + c];
                acc += q[c * 4 + 0] * k4.x;
                acc += q[c * 4 + 1] * k4.y;
                acc += q[c * 4 + 2] * k4.z;
                acc += q[c * 4 + 3] * k4.w;
            }
            float s = acc * SCALE;

            if (s > m) {                       // rare: new running max
                float alpha = __expf(m - s);
                l *= alpha;
#pragma unroll
                for (int d = 0; d < HD; d++) o[d] *= alpha;
                m = s;
            }
            float p = __expf(s - m);
            l += p;
#pragma unroll
            for (int c = 0; c < 12; c++) {
                float4 v4 = Vs[j * 12 + c];
                o[c * 4 + 0] += p * v4.x;
                o[c * 4 + 1] += p * v4.y;
                o[c * 4 + 2] += p * v4.z;
                o[c * 4 + 3] += p * v4.w;
            }
        }
    }

    float inv_l = 1.f / l;
    float* xptr = X + (size_t)t * CC + h * HD;
#pragma unroll
    for (int c = 0; c < 12; c++) {
        float4 f;
        f.x = o[c * 4 + 0] * inv_l;
        f.y = o[c * 4 + 1] * inv_l;
        f.z = o[c * 4 + 2] * inv_l;
        f.w = o[c * 4 + 3] * inv_l;
        ((float4*)xptr)[c] = f;
    }
}

// ---------------------------------------------------------------------------
// Launch
// ---------------------------------------------------------------------------
extern "C" void kernel_launch(void* const* d_in, const int* in_sizes, int n_in,
                              void* d_out, int out_size)
{
    const float* query = (const float*)d_in[0];
    const float* key   = (const float*)d_in[1];
    const float* value = (const float*)d_in[2];
    const float* Wq = (const float*)d_in[3];
    const float* bq = (const float*)d_in[4];
    const float* Wk = (const float*)d_in[5];
    const float* bk = (const float*)d_in[6];
    const float* Wv = (const float*)d_in[7];
    const float* bv = (const float*)d_in[8];
    const float* Wo = (const float*)d_in[9];
    const float* bo = (const float*)d_in[10];
    const int* qpos = (const int*)d_in[11];
    const int* kpos = (const int*)d_in[12];
    // d_in[13], d_in[14]: equal-length segment offsets — statically known here.
    float* out = (float*)d_out;

    float *pQ, *pK, *pV, *pX;
    cudaGetSymbolAddress((void**)&pQ, g_Q);
    cudaGetSymbolAddress((void**)&pK, g_K);
    cudaGetSymbolAddress((void**)&pV, g_V);
    cudaGetSymbolAddress((void**)&pX, g_X);

    dim3 ggrid(CC / 64, TT / 64);   // (6, 128)

    gemm_nt_bias<<<ggrid, 256>>>(query, Wq, bq, pQ);
    gemm_nt_bias<<<ggrid, 256>>>(key,   Wk, bk, pK);
    gemm_nt_bias<<<ggrid, 256>>>(value, Wv, bv, pV);

    int rope_threads = TT * HH * 3;
    rope3d_kernel<<<(rope_threads + 255) / 256, 256>>>(pQ, qpos);
    rope3d_kernel<<<(rope_threads + 255) / 256, 256>>>(pK, kpos);

    attn_kernel<<<dim3(NN / 128, HH, BB), 128>>>(pQ, pK, pV, pX);

    gemm_nt_bias<<<ggrid, 256>>>(pX, Wo, bo, out);
}